// round 15
// baseline (speedup 1.0000x reference)
#include <cuda_runtime.h>
#include <cuda_fp16.h>
#include <cstdint>
#include <math.h>

// Problem constants
#define B_BATCH 4
#define S_SEQ   1024
#define H_DIM   1024
#define I_DIM   768
#define E_NUM   8
#define T_TOK   4096
#define TKS     8192

#define BM        128
#define MAX_TILES 72
#define WELEM     (E_NUM * I_DIM * H_DIM)     // 6291456
#define XN4       (T_TOK * H_DIM / 4)         // 1048576
#define WN4       (WELEM / 4)                 // 1572864

// ---------------- device scratch (fp16 packed as uint32 pairs) -----------
__device__ int      g_ntiles;
__device__ int      g_tile_e[MAX_TILES];
__device__ int      g_tile_row[MAX_TILES];
__device__ int      g_tile_m[MAX_TILES];
__device__ int      g_tok[TKS];
__device__ int      g_slotpos[TKS];
__device__ uint32_t g_x16[T_TOK * H_DIM / 2];        // fp16x2
__device__ uint32_t g_wg[WELEM / 2];
__device__ uint32_t g_wu[WELEM / 2];
__device__ uint32_t g_wd[WELEM / 2];
__device__ uint32_t g_h16[(size_t)TKS * I_DIM / 2];
__device__ uint32_t g_y16[(size_t)TKS * H_DIM / 2];  // fp16 y

// ---------------- helpers ----------------
__device__ __forceinline__ uint32_t smem_u32(const void* p) {
    uint32_t r;
    asm("{ .reg .u64 t; cvta.to.shared.u64 t, %1; cvt.u32.u64 %0, t; }"
        : "=r"(r) : "l"(p));
    return r;
}
__device__ __forceinline__ void cp16(uint32_t dst, const void* src) {
    asm volatile("cp.async.cg.shared.global [%0], [%1], 16;"
                 :: "r"(dst), "l"(__cvta_generic_to_global(src)) : "memory");
}
#define CP_COMMIT() asm volatile("cp.async.commit_group;" ::: "memory")

__device__ __forceinline__ void ldmx4(uint32_t* r, uint32_t a) {
    asm volatile("ldmatrix.sync.aligned.m8n8.x4.shared.b16 {%0,%1,%2,%3}, [%4];"
                 : "=r"(r[0]), "=r"(r[1]), "=r"(r[2]), "=r"(r[3]) : "r"(a));
}
__device__ __forceinline__ void mma_f16(float* d, const uint32_t* a,
                                        uint32_t b0, uint32_t b1) {
    asm volatile(
        "mma.sync.aligned.m16n8k16.row.col.f32.f16.f16.f32 "
        "{%0,%1,%2,%3}, {%4,%5,%6,%7}, {%8,%9}, {%0,%1,%2,%3};"
        : "+f"(d[0]), "+f"(d[1]), "+f"(d[2]), "+f"(d[3])
        : "r"(a[0]), "r"(a[1]), "r"(a[2]), "r"(a[3]), "r"(b0), "r"(b1));
}
__device__ __forceinline__ uint32_t pack_f16(float a, float b) {
    __half2 t = __floats2half2_rn(a, b);
    return *reinterpret_cast<uint32_t*>(&t);
}

// ---------------- routing body (runs as one block of cvt_route) ----------
__device__ void route_body(const void* __restrict__ se_raw) {
    __shared__ int s_cnt[E_NUM];
    __shared__ int s_pos[E_NUM];
    __shared__ int s_bad;
    int tid = threadIdx.x;
    if (tid == 0) s_bad = 0;
    if (tid < E_NUM) s_cnt[tid] = 0;
    __syncthreads();
    const long long* se64 = (const long long*)se_raw;
    const int*       se32 = (const int*)se_raw;
    int bad = 0;
    for (int i = tid; i < 2048; i += blockDim.x) {
        long long v = se64[i];
        if (v < 0 || v >= E_NUM) bad = 1;
    }
    if (bad) atomicOr(&s_bad, 1);
    __syncthreads();
    const int is64 = s_bad ? 0 : 1;
    for (int s = tid; s < TKS; s += blockDim.x) {
        int e = is64 ? (int)se64[s] : se32[s];
        atomicAdd(&s_cnt[e], 1);
    }
    __syncthreads();
    if (tid == 0) {
        int off = 0, nt = 0;
        for (int e = 0; e < E_NUM; e++) {
            int c = s_cnt[e];
            s_pos[e] = off;
            for (int r = 0; r < c; r += BM) {
                g_tile_e[nt]   = e;
                g_tile_row[nt] = off + r;
                g_tile_m[nt]   = min(BM, c - r);
                nt++;
            }
            off += c;
        }
        g_ntiles = nt;
    }
    __syncthreads();
    for (int s = tid; s < TKS; s += blockDim.x) {
        int e = is64 ? (int)se64[s] : se32[s];
        int pos = atomicAdd(&s_pos[e], 1);
        g_tok[pos]   = s >> 1;
        g_slotpos[s] = pos;
    }
}

// ---------------- prep: fp32 -> fp16 (MLP=8) + routing in last block -----
__global__ void cvt_route(const float4* __restrict__ x,  const float4* __restrict__ wg,
                          const float4* __restrict__ wu, const float4* __restrict__ wd,
                          const void* __restrict__ se) {
    int b = blockIdx.x;
    if (b == 2816) { route_body(se); return; }
    const float4* src;
    uint2* dst;
    int base;
    if (b < 512)       { src = x;  dst = (uint2*)g_x16; base = b * 2048; }
    else if (b < 1280) { src = wg; dst = (uint2*)g_wg;  base = (b - 512)  * 2048; }
    else if (b < 2048) { src = wu; dst = (uint2*)g_wu;  base = (b - 1280) * 2048; }
    else               { src = wd; dst = (uint2*)g_wd;  base = (b - 2048) * 2048; }
    const int i = base + threadIdx.x;
    float4 v[8];
#pragma unroll
    for (int r = 0; r < 8; r++) v[r] = src[i + r * 256];
#pragma unroll
    for (int r = 0; r < 8; r++)
        dst[i + r * 256] = make_uint2(pack_f16(v[r].x, v[r].y),
                                      pack_f16(v[r].z, v[r].w));
}

// ---------------- GEMM1: gate+up fused, SiLU epilogue --------------------
// CTA 128x64 (x2 matrices), 4 warps (2m x 2n), warp tile 64x32 per matrix.
// Warp skips MMA work entirely when its 64-row range is fully padded.
#define ST1 20480
__global__ __launch_bounds__(128, 3) void gemm1_hmma() {
    extern __shared__ char dsm[];
    const int tile = blockIdx.y;
    if (tile >= g_ntiles) return;
    const int e    = g_tile_e[tile];
    const int row0 = g_tile_row[tile];
    const int mcnt = g_tile_m[tile];
    const int n0   = blockIdx.x * 64;
    const int tid  = threadIdx.x, lane = tid & 31, wid = tid >> 5;
    const int wm   = wid & 1, wn = wid >> 1;
    const bool act = (wm * 64) < mcnt;    // warp-uniform skip flag
    const uint32_t sbase = smem_u32(dsm);

    const int tokA = g_tok[row0 + min(tid, mcnt - 1)];
    const char* asrc = (const char*)g_x16 + (size_t)tokA * (H_DIM * 2);
    const uint32_t adst = sbase + tid * 80;
    const bool gate = tid < 64;
    const int br = gate ? tid : tid - 64;
    const char* bsrc = (const char*)(gate ? g_wg : g_wu)
                       + (size_t)(e * I_DIM + n0 + br) * (H_DIM * 2);
    const uint32_t bdst = sbase + (gate ? 10240 : 15360) + br * 80;

    const int arow_l = (lane & 7) + ((lane >> 3) & 1) * 8;
    const uint32_t akb   = (lane >> 4) * 16;
    const uint32_t aoff  = (wm * 64 + arow_l) * 80 + akb;
    const uint32_t bgoff = 10240 + (wn * 32 + lane) * 80;
    const uint32_t buoff = 15360 + (wn * 32 + lane) * 80;

    float accg[64], accu[64];
#pragma unroll
    for (int i = 0; i < 64; i++) { accg[i] = 0.f; accu[i] = 0.f; }

    const int NC = H_DIM / 32;   // 32
#pragma unroll
    for (int s = 0; s < 2; s++) {
        const char* as = asrc + s * 64;
        const char* bs = bsrc + s * 64;
#pragma unroll
        for (int j = 0; j < 4; j++) cp16(adst + s * ST1 + j * 16, as + j * 16);
#pragma unroll
        for (int j = 0; j < 4; j++) cp16(bdst + s * ST1 + j * 16, bs + j * 16);
        CP_COMMIT();
    }

    for (int c = 0; c < NC; c++) {
        asm volatile("cp.async.wait_group 1;" ::: "memory");
        __syncthreads();
        const uint32_t buf = sbase + (c % 3) * ST1;
        if (act) {
#pragma unroll
            for (int kk = 0; kk < 2; kk++) {
                const uint32_t ko = kk * 32;
                uint32_t A[4][4];
#pragma unroll
                for (int ms = 0; ms < 4; ms++)
                    ldmx4(A[ms], buf + aoff + ms * (16 * 80) + ko);
                uint32_t Bg0[4], Bg1[4], Bu0[4], Bu1[4];
                ldmx4(Bg0, buf + bgoff + ko);
                ldmx4(Bg1, buf + bgoff + ko + 16);
                ldmx4(Bu0, buf + buoff + ko);
                ldmx4(Bu1, buf + buoff + ko + 16);
#pragma unroll
                for (int ms = 0; ms < 4; ms++)
#pragma unroll
                for (int nt = 0; nt < 4; nt++) {
                    mma_f16(accg + ms * 16 + nt * 4, A[ms], Bg0[nt], Bg1[nt]);
                    mma_f16(accu + ms * 16 + nt * 4, A[ms], Bu0[nt], Bu1[nt]);
                }
            }
        }
        if (c + 2 < NC) {
            const uint32_t bo = ((c + 2) % 3) * ST1;
            const char* as = asrc + (size_t)(c + 2) * 64;
            const char* bs = bsrc + (size_t)(c + 2) * 64;
#pragma unroll
            for (int j = 0; j < 4; j++) cp16(adst + bo + j * 16, as + j * 16);
#pragma unroll
            for (int j = 0; j < 4; j++) cp16(bdst + bo + j * 16, bs + j * 16);
        }
        CP_COMMIT();
    }

    // epilogue: h = silu(g) * u -> fp16
    if (act) {
#pragma unroll
        for (int ms = 0; ms < 4; ms++)
#pragma unroll
        for (int nt = 0; nt < 4; nt++) {
            const int mB   = wm * 64 + ms * 16 + (lane >> 2);
            const int gcol = n0 + wn * 32 + nt * 8 + (lane & 3) * 2;
            const float* dg = accg + ms * 16 + nt * 4;
            const float* du = accu + ms * 16 + nt * 4;
#pragma unroll
            for (int half = 0; half < 2; half++) {
                const int m = mB + half * 8;
                if (m < mcnt) {
                    float g0 = dg[half * 2], g1 = dg[half * 2 + 1];
                    float u0 = du[half * 2], u1 = du[half * 2 + 1];
                    float h0 = g0 / (1.f + __expf(-g0)) * u0;
                    float h1 = g1 / (1.f + __expf(-g1)) * u1;
                    g_h16[((size_t)(row0 + m) * I_DIM + gcol) >> 1] = pack_f16(h0, h1);
                }
            }
        }
    }
}

// ---------------- GEMM2: down projection, fp16 y epilogue ----------------
// CTA 128x128, 8 warps (4m x 2n), warp 32x64. Warp skips MMA work when its
// 32-row range is fully padded.
#define ST2 20480
__global__ __launch_bounds__(256, 2) void gemm2_hmma() {
    extern __shared__ char dsm[];
    const int tile = blockIdx.y;
    if (tile >= g_ntiles) return;
    const int e    = g_tile_e[tile];
    const int row0 = g_tile_row[tile];
    const int mcnt = g_tile_m[tile];
    const int n0   = blockIdx.x * 128;
    const int tid  = threadIdx.x, lane = tid & 31, wid = tid >> 5;
    const int wm   = wid & 3, wn = wid >> 2;   // wn in {0,1}
    const bool act = (wm * 32) < mcnt;    // warp-uniform skip flag
    const uint32_t sbase = smem_u32(dsm);

    const int crow = tid & 127;
    const char* csrc;
    uint32_t cdst;
    if (tid < 128) {
        int arow = row0 + min(crow, mcnt - 1);
        csrc = (const char*)g_h16 + (size_t)arow * (I_DIM * 2);
        cdst = sbase + crow * 80;
    } else {
        csrc = (const char*)g_wd + (size_t)(e * H_DIM + n0 + crow) * (I_DIM * 2);
        cdst = sbase + 10240 + crow * 80;
    }

    const int arow_l = (lane & 7) + ((lane >> 3) & 1) * 8;
    const uint32_t akb   = (lane >> 4) * 16;
    const uint32_t aoff  = (wm * 32 + arow_l) * 80 + akb;
    const uint32_t boffa = 10240 + (wn * 64 + lane) * 80;
    const uint32_t boffb = 10240 + (wn * 64 + 32 + lane) * 80;

    float acc[64];
#pragma unroll
    for (int i = 0; i < 64; i++) acc[i] = 0.f;

    const int NC = I_DIM / 32;   // 24
#pragma unroll
    for (int s = 0; s < 3; s++) {
        const uint32_t d = cdst + s * ST2;
        const char* sc = csrc + s * 64;
#pragma unroll
        for (int j = 0; j < 4; j++) cp16(d + j * 16, sc + j * 16);
        CP_COMMIT();
    }

    for (int c = 0; c < NC; c++) {
        asm volatile("cp.async.wait_group 2;" ::: "memory");
        __syncthreads();
        const uint32_t buf = sbase + (c & 3) * ST2;
        if (act) {
#pragma unroll
            for (int kk = 0; kk < 2; kk++) {
                const uint32_t ko = kk * 32;
                uint32_t Ah[2][4];
                ldmx4(Ah[0], buf + aoff + ko);
                ldmx4(Ah[1], buf + aoff + 16 * 80 + ko);
                uint32_t Ba0[4], Ba1[4], Bb0[4], Bb1[4];
                ldmx4(Ba0, buf + boffa + ko);
                ldmx4(Ba1, buf + boffa + ko + 16);
                ldmx4(Bb0, buf + boffb + ko);
                ldmx4(Bb1, buf + boffb + ko + 16);
#pragma unroll
                for (int mt = 0; mt < 2; mt++) {
#pragma unroll
                    for (int nt = 0; nt < 4; nt++)
                        mma_f16(acc + mt * 32 + nt * 4, Ah[mt], Ba0[nt], Ba1[nt]);
#pragma unroll
                    for (int nt = 0; nt < 4; nt++)
                        mma_f16(acc + mt * 32 + 16 + nt * 4, Ah[mt], Bb0[nt], Bb1[nt]);
                }
            }
        }
        if (c + 3 < NC) {
            const uint32_t d = cdst + ((c + 3) & 3) * ST2;
            const char* sc = csrc + (size_t)(c + 3) * 64;
#pragma unroll
            for (int j = 0; j < 4; j++) cp16(d + j * 16, sc + j * 16);
        }
        CP_COMMIT();
    }

    if (act) {
#pragma unroll
        for (int mt = 0; mt < 2; mt++)
#pragma unroll
        for (int nt = 0; nt < 8; nt++) {
            const int mB   = wm * 32 + mt * 16 + (lane >> 2);
            const int gcol = n0 + wn * 64 + nt * 8 + (lane & 3) * 2;
            const float* d = acc + mt * 32 + nt * 4;
#pragma unroll
            for (int half = 0; half < 2; half++) {
                const int m = mB + half * 8;
                if (m < mcnt) {
                    g_y16[((size_t)(row0 + m) * H_DIM + gcol) >> 1] =
                        pack_f16(d[half * 2], d[half * 2 + 1]);
                }
            }
        }
    }
}

// ---------------- combine: 4 tokens per block, MLP=8 ---------------------
__global__ void combine_kernel(const float* __restrict__ rw, float4* __restrict__ out)
{
    const int tid = threadIdx.x;
    const int t  = blockIdx.x * 4 + (tid >> 6);
    const int c0 = tid & 63;
    const float w0 = rw[2 * t];
    const float w1 = rw[2 * t + 1];
    const int p0 = g_slotpos[2 * t];
    const int p1 = g_slotpos[2 * t + 1];
    const uint2* ya = (const uint2*)g_y16 + (size_t)p0 * 256;
    const uint2* yb = (const uint2*)g_y16 + (size_t)p1 * 256;
    uint2 a[4], b[4];
#pragma unroll
    for (int r = 0; r < 4; r++) { a[r] = ya[c0 + r * 64]; b[r] = yb[c0 + r * 64]; }
#pragma unroll
    for (int r = 0; r < 4; r++) {
        float2 a0 = __half22float2(*reinterpret_cast<__half2*>(&a[r].x));
        float2 a1 = __half22float2(*reinterpret_cast<__half2*>(&a[r].y));
        float2 b0 = __half22float2(*reinterpret_cast<__half2*>(&b[r].x));
        float2 b1 = __half22float2(*reinterpret_cast<__half2*>(&b[r].y));
        out[(size_t)t * 256 + c0 + r * 64] =
            make_float4(w0 * a0.x + w1 * b0.x,
                        w0 * a0.y + w1 * b0.y,
                        w0 * a1.x + w1 * b1.x,
                        w0 * a1.y + w1 * b1.y);
    }
}

// ---------------- launch ---------------------------------------------------
extern "C" void kernel_launch(void* const* d_in, const int* in_sizes, int n_in,
                              void* d_out, int out_size)
{
    const float* x   = (const float*)d_in[0];
    const float* rw  = (const float*)d_in[1];
    const void*  se  = d_in[2];
    const float* Wg  = (const float*)d_in[3];
    const float* Wu  = (const float*)d_in[4];
    const float* Wd  = (const float*)d_in[5];
    float*       out = (float*)d_out;

    const int SM1 = 3 * ST1;   // 61440
    const int SM2 = 4 * ST2;   // 81920
    cudaFuncSetAttribute(gemm1_hmma, cudaFuncAttributeMaxDynamicSharedMemorySize, SM1);
    cudaFuncSetAttribute(gemm2_hmma, cudaFuncAttributeMaxDynamicSharedMemorySize, SM2);

    cvt_route<<<2817, 256>>>((const float4*)x, (const float4*)Wg,
                             (const float4*)Wu, (const float4*)Wd, se);
    gemm1_hmma<<<dim3(I_DIM / 64, MAX_TILES), 128, SM1>>>();
    gemm2_hmma<<<dim3(H_DIM / 128, MAX_TILES), 256, SM2>>>();
    combine_kernel<<<T_TOK / 4, 256>>>(rw, (float4*)out);
    (void)in_sizes; (void)n_in; (void)out_size;
}

// round 16
// speedup vs baseline: 1.0622x; 1.0622x over previous
#include <cuda_runtime.h>
#include <cuda_fp16.h>
#include <cstdint>
#include <math.h>

// Problem constants
#define B_BATCH 4
#define S_SEQ   1024
#define H_DIM   1024
#define I_DIM   768
#define E_NUM   8
#define T_TOK   4096
#define TKS     8192

#define BM        128
#define MAX_TILES 72
#define WELEM     (E_NUM * I_DIM * H_DIM)     // 6291456
#define XN4       (T_TOK * H_DIM / 4)         // 1048576
#define WN4       (WELEM / 4)                 // 1572864

// ---------------- device scratch (fp16 packed as uint32 pairs) -----------
__device__ int      g_ntiles;
__device__ int      g_tile_e[MAX_TILES];
__device__ int      g_tile_row[MAX_TILES];
__device__ int      g_tile_m[MAX_TILES];
__device__ int      g_tok[TKS];
__device__ int      g_slotpos[TKS];
__device__ uint32_t g_x16[T_TOK * H_DIM / 2];        // fp16x2
__device__ uint32_t g_wg[WELEM / 2];
__device__ uint32_t g_wu[WELEM / 2];
__device__ uint32_t g_wd[WELEM / 2];
__device__ uint32_t g_h16[(size_t)TKS * I_DIM / 2];
__device__ uint32_t g_y16[(size_t)TKS * H_DIM / 2];  // fp16 y

// ---------------- helpers ----------------
__device__ __forceinline__ uint32_t smem_u32(const void* p) {
    uint32_t r;
    asm("{ .reg .u64 t; cvta.to.shared.u64 t, %1; cvt.u32.u64 %0, t; }"
        : "=r"(r) : "l"(p));
    return r;
}
__device__ __forceinline__ void cp16(uint32_t dst, const void* src) {
    asm volatile("cp.async.cg.shared.global [%0], [%1], 16;"
                 :: "r"(dst), "l"(__cvta_generic_to_global(src)) : "memory");
}
#define CP_COMMIT() asm volatile("cp.async.commit_group;" ::: "memory")

__device__ __forceinline__ void ldmx4(uint32_t* r, uint32_t a) {
    asm volatile("ldmatrix.sync.aligned.m8n8.x4.shared.b16 {%0,%1,%2,%3}, [%4];"
                 : "=r"(r[0]), "=r"(r[1]), "=r"(r[2]), "=r"(r[3]) : "r"(a));
}
__device__ __forceinline__ void mma_f16(float* d, const uint32_t* a,
                                        uint32_t b0, uint32_t b1) {
    asm volatile(
        "mma.sync.aligned.m16n8k16.row.col.f32.f16.f16.f32 "
        "{%0,%1,%2,%3}, {%4,%5,%6,%7}, {%8,%9}, {%0,%1,%2,%3};"
        : "+f"(d[0]), "+f"(d[1]), "+f"(d[2]), "+f"(d[3])
        : "r"(a[0]), "r"(a[1]), "r"(a[2]), "r"(a[3]), "r"(b0), "r"(b1));
}
__device__ __forceinline__ uint32_t pack_f16(float a, float b) {
    __half2 t = __floats2half2_rn(a, b);
    return *reinterpret_cast<uint32_t*>(&t);
}

// ---------------- routing body (runs as one block of cvt_route) ----------
__device__ void route_body(const void* __restrict__ se_raw) {
    __shared__ int s_cnt[E_NUM];
    __shared__ int s_pos[E_NUM];
    __shared__ int s_bad;
    int tid = threadIdx.x;
    if (tid == 0) s_bad = 0;
    if (tid < E_NUM) s_cnt[tid] = 0;
    __syncthreads();
    const long long* se64 = (const long long*)se_raw;
    const int*       se32 = (const int*)se_raw;
    int bad = 0;
    for (int i = tid; i < 2048; i += blockDim.x) {
        long long v = se64[i];
        if (v < 0 || v >= E_NUM) bad = 1;
    }
    if (bad) atomicOr(&s_bad, 1);
    __syncthreads();
    const int is64 = s_bad ? 0 : 1;
    for (int s = tid; s < TKS; s += blockDim.x) {
        int e = is64 ? (int)se64[s] : se32[s];
        atomicAdd(&s_cnt[e], 1);
    }
    __syncthreads();
    if (tid == 0) {
        int off = 0, nt = 0;
        for (int e = 0; e < E_NUM; e++) {
            int c = s_cnt[e];
            s_pos[e] = off;
            for (int r = 0; r < c; r += BM) {
                g_tile_e[nt]   = e;
                g_tile_row[nt] = off + r;
                g_tile_m[nt]   = min(BM, c - r);
                nt++;
            }
            off += c;
        }
        g_ntiles = nt;
    }
    __syncthreads();
    for (int s = tid; s < TKS; s += blockDim.x) {
        int e = is64 ? (int)se64[s] : se32[s];
        int pos = atomicAdd(&s_pos[e], 1);
        g_tok[pos]   = s >> 1;
        g_slotpos[s] = pos;
    }
}

// ---------------- prep: x/wg/wu fp32 -> fp16 (MLP=8) + routing -----------
// Blocks [0,512): x; [512,1280): wg; [1280,2048): wu; block 2048: routing.
// (wd conversion rides inside gemm1's grid on idle DRAM bandwidth.)
__global__ void cvt_route(const float4* __restrict__ x,  const float4* __restrict__ wg,
                          const float4* __restrict__ wu, const void* __restrict__ se) {
    int b = blockIdx.x;
    if (b == 2048) { route_body(se); return; }
    const float4* src;
    uint2* dst;
    int base;
    if (b < 512)       { src = x;  dst = (uint2*)g_x16; base = b * 2048; }
    else if (b < 1280) { src = wg; dst = (uint2*)g_wg;  base = (b - 512)  * 2048; }
    else               { src = wu; dst = (uint2*)g_wu;  base = (b - 1280) * 2048; }
    const int i = base + threadIdx.x;
    float4 v[8];
#pragma unroll
    for (int r = 0; r < 8; r++) v[r] = src[i + r * 256];
#pragma unroll
    for (int r = 0; r < 8; r++)
        dst[i + r * 256] = make_uint2(pack_f16(v[r].x, v[r].y),
                                      pack_f16(v[r].z, v[r].w));
}

// ---------------- GEMM1 (r14 inner loop) + wd-conversion blocks ----------
// Tiles: blockIdx.y < MAX_TILES. Conversion role: blockIdx.y >= MAX_TILES
// (768 blocks convert Wd fp32->fp16 on gemm1's idle DRAM bandwidth).
// CTA 128x64 (x2 matrices), 4 warps (2m x 2n), warp tile 64x32 per matrix.
// K=1024 in 32 chunks of K=32 (64B data/row, 80B pitch). Stage:
//   A rows 0-127 @0 (10240), Bg @10240 (5120), Bu @15360 (5120).
// Stage stride 20480, 3 stages = 61440 B. 128 threads.
#define ST1 20480
#define CONV_Y 64   // 64 extra grid.y rows x 12 grid.x = 768 conversion blocks
__global__ __launch_bounds__(128, 3) void gemm1_hmma(const float4* __restrict__ wd) {
    extern __shared__ char dsm[];
    const int tile = blockIdx.y;
    if (tile >= MAX_TILES) {
        // Wd conversion role: cid in [0,768), 2048 float4 per block.
        const int cid  = (tile - MAX_TILES) * gridDim.x + blockIdx.x;
        const int base = cid * 2048;
        uint2* dst = (uint2*)g_wd;
#pragma unroll
        for (int h = 0; h < 2; h++) {
            const int i = base + h * 1024 + threadIdx.x;
            float4 v[8];
#pragma unroll
            for (int r = 0; r < 8; r++) v[r] = wd[i + r * 128];
#pragma unroll
            for (int r = 0; r < 8; r++)
                dst[i + r * 128] = make_uint2(pack_f16(v[r].x, v[r].y),
                                              pack_f16(v[r].z, v[r].w));
        }
        return;
    }
    if (tile >= g_ntiles) return;
    const int e    = g_tile_e[tile];
    const int row0 = g_tile_row[tile];
    const int mcnt = g_tile_m[tile];
    const int n0   = blockIdx.x * 64;
    const int tid  = threadIdx.x, lane = tid & 31, wid = tid >> 5;
    const int wm   = wid & 1, wn = wid >> 1;
    const uint32_t sbase = smem_u32(dsm);

    const int tokA = g_tok[row0 + min(tid, mcnt - 1)];
    const char* asrc = (const char*)g_x16 + (size_t)tokA * (H_DIM * 2);
    const uint32_t adst = sbase + tid * 80;
    const bool gate = tid < 64;
    const int br = gate ? tid : tid - 64;
    const char* bsrc = (const char*)(gate ? g_wg : g_wu)
                       + (size_t)(e * I_DIM + n0 + br) * (H_DIM * 2);
    const uint32_t bdst = sbase + (gate ? 10240 : 15360) + br * 80;

    const int arow_l = (lane & 7) + ((lane >> 3) & 1) * 8;
    const uint32_t akb   = (lane >> 4) * 16;
    const uint32_t aoff  = (wm * 64 + arow_l) * 80 + akb;
    const uint32_t bgoff = 10240 + (wn * 32 + lane) * 80;
    const uint32_t buoff = 15360 + (wn * 32 + lane) * 80;

    float accg[64], accu[64];
#pragma unroll
    for (int i = 0; i < 64; i++) { accg[i] = 0.f; accu[i] = 0.f; }

    const int NC = H_DIM / 32;   // 32
#pragma unroll
    for (int s = 0; s < 2; s++) {
        const char* as = asrc + s * 64;
        const char* bs = bsrc + s * 64;
#pragma unroll
        for (int j = 0; j < 4; j++) cp16(adst + s * ST1 + j * 16, as + j * 16);
#pragma unroll
        for (int j = 0; j < 4; j++) cp16(bdst + s * ST1 + j * 16, bs + j * 16);
        CP_COMMIT();
    }

    for (int c = 0; c < NC; c++) {
        asm volatile("cp.async.wait_group 1;" ::: "memory");
        __syncthreads();
        const uint32_t buf = sbase + (c % 3) * ST1;
#pragma unroll
        for (int kk = 0; kk < 2; kk++) {
            const uint32_t ko = kk * 32;
            uint32_t A[4][4];
#pragma unroll
            for (int ms = 0; ms < 4; ms++)
                ldmx4(A[ms], buf + aoff + ms * (16 * 80) + ko);
            uint32_t Bg0[4], Bg1[4], Bu0[4], Bu1[4];
            ldmx4(Bg0, buf + bgoff + ko);
            ldmx4(Bg1, buf + bgoff + ko + 16);
            ldmx4(Bu0, buf + buoff + ko);
            ldmx4(Bu1, buf + buoff + ko + 16);
#pragma unroll
            for (int ms = 0; ms < 4; ms++)
#pragma unroll
            for (int nt = 0; nt < 4; nt++) {
                mma_f16(accg + ms * 16 + nt * 4, A[ms], Bg0[nt], Bg1[nt]);
                mma_f16(accu + ms * 16 + nt * 4, A[ms], Bu0[nt], Bu1[nt]);
            }
        }
        if (c + 2 < NC) {
            const uint32_t bo = ((c + 2) % 3) * ST1;
            const char* as = asrc + (size_t)(c + 2) * 64;
            const char* bs = bsrc + (size_t)(c + 2) * 64;
#pragma unroll
            for (int j = 0; j < 4; j++) cp16(adst + bo + j * 16, as + j * 16);
#pragma unroll
            for (int j = 0; j < 4; j++) cp16(bdst + bo + j * 16, bs + j * 16);
        }
        CP_COMMIT();
    }

    // epilogue: h = silu(g) * u -> fp16
#pragma unroll
    for (int ms = 0; ms < 4; ms++)
#pragma unroll
    for (int nt = 0; nt < 4; nt++) {
        const int mB   = wm * 64 + ms * 16 + (lane >> 2);
        const int gcol = n0 + wn * 32 + nt * 8 + (lane & 3) * 2;
        const float* dg = accg + ms * 16 + nt * 4;
        const float* du = accu + ms * 16 + nt * 4;
#pragma unroll
        for (int half = 0; half < 2; half++) {
            const int m = mB + half * 8;
            if (m < mcnt) {
                float g0 = dg[half * 2], g1 = dg[half * 2 + 1];
                float u0 = du[half * 2], u1 = du[half * 2 + 1];
                float h0 = g0 / (1.f + __expf(-g0)) * u0;
                float h1 = g1 / (1.f + __expf(-g1)) * u1;
                g_h16[((size_t)(row0 + m) * I_DIM + gcol) >> 1] = pack_f16(h0, h1);
            }
        }
    }
}

// ---------------- GEMM2 (r14 exact): down projection, fp16 y -------------
// CTA 128x128, 8 warps (4m x 2n), warp 32x64. K=768 in 24 chunks of K=32
// (64B data/row, 80B pitch). Stage stride 20480, 4 stages. 2 CTAs/SM.
#define ST2 20480
__global__ __launch_bounds__(256, 2) void gemm2_hmma() {
    extern __shared__ char dsm[];
    const int tile = blockIdx.y;
    if (tile >= g_ntiles) return;
    const int e    = g_tile_e[tile];
    const int row0 = g_tile_row[tile];
    const int mcnt = g_tile_m[tile];
    const int n0   = blockIdx.x * 128;
    const int tid  = threadIdx.x, lane = tid & 31, wid = tid >> 5;
    const int wm   = wid & 3, wn = wid >> 2;   // wn in {0,1}
    const uint32_t sbase = smem_u32(dsm);

    const int crow = tid & 127;
    const char* csrc;
    uint32_t cdst;
    if (tid < 128) {
        int arow = row0 + min(crow, mcnt - 1);
        csrc = (const char*)g_h16 + (size_t)arow * (I_DIM * 2);
        cdst = sbase + crow * 80;
    } else {
        csrc = (const char*)g_wd + (size_t)(e * H_DIM + n0 + crow) * (I_DIM * 2);
        cdst = sbase + 10240 + crow * 80;
    }

    const int arow_l = (lane & 7) + ((lane >> 3) & 1) * 8;
    const uint32_t akb   = (lane >> 4) * 16;
    const uint32_t aoff  = (wm * 32 + arow_l) * 80 + akb;
    const uint32_t boffa = 10240 + (wn * 64 + lane) * 80;
    const uint32_t boffb = 10240 + (wn * 64 + 32 + lane) * 80;

    float acc[64];
#pragma unroll
    for (int i = 0; i < 64; i++) acc[i] = 0.f;

    const int NC = I_DIM / 32;   // 24
#pragma unroll
    for (int s = 0; s < 3; s++) {
        const uint32_t d = cdst + s * ST2;
        const char* sc = csrc + s * 64;
#pragma unroll
        for (int j = 0; j < 4; j++) cp16(d + j * 16, sc + j * 16);
        CP_COMMIT();
    }

    for (int c = 0; c < NC; c++) {
        asm volatile("cp.async.wait_group 2;" ::: "memory");
        __syncthreads();
        const uint32_t buf = sbase + (c & 3) * ST2;
#pragma unroll
        for (int kk = 0; kk < 2; kk++) {
            const uint32_t ko = kk * 32;
            uint32_t Ah[2][4];
            ldmx4(Ah[0], buf + aoff + ko);
            ldmx4(Ah[1], buf + aoff + 16 * 80 + ko);
            uint32_t Ba0[4], Ba1[4], Bb0[4], Bb1[4];
            ldmx4(Ba0, buf + boffa + ko);
            ldmx4(Ba1, buf + boffa + ko + 16);
            ldmx4(Bb0, buf + boffb + ko);
            ldmx4(Bb1, buf + boffb + ko + 16);
#pragma unroll
            for (int mt = 0; mt < 2; mt++) {
#pragma unroll
                for (int nt = 0; nt < 4; nt++)
                    mma_f16(acc + mt * 32 + nt * 4, Ah[mt], Ba0[nt], Ba1[nt]);
#pragma unroll
                for (int nt = 0; nt < 4; nt++)
                    mma_f16(acc + mt * 32 + 16 + nt * 4, Ah[mt], Bb0[nt], Bb1[nt]);
            }
        }
        if (c + 3 < NC) {
            const uint32_t d = cdst + ((c + 3) & 3) * ST2;
            const char* sc = csrc + (size_t)(c + 3) * 64;
#pragma unroll
            for (int j = 0; j < 4; j++) cp16(d + j * 16, sc + j * 16);
        }
        CP_COMMIT();
    }

#pragma unroll
    for (int mt = 0; mt < 2; mt++)
#pragma unroll
    for (int nt = 0; nt < 8; nt++) {
        const int mB   = wm * 32 + mt * 16 + (lane >> 2);
        const int gcol = n0 + wn * 64 + nt * 8 + (lane & 3) * 2;
        const float* d = acc + mt * 32 + nt * 4;
#pragma unroll
        for (int half = 0; half < 2; half++) {
            const int m = mB + half * 8;
            if (m < mcnt) {
                g_y16[((size_t)(row0 + m) * H_DIM + gcol) >> 1] =
                    pack_f16(d[half * 2], d[half * 2 + 1]);
            }
        }
    }
}

// ---------------- combine: 4 tokens per block, MLP=8 (r15, kept) ---------
__global__ void combine_kernel(const float* __restrict__ rw, float4* __restrict__ out)
{
    const int tid = threadIdx.x;
    const int t  = blockIdx.x * 4 + (tid >> 6);
    const int c0 = tid & 63;
    const float w0 = rw[2 * t];
    const float w1 = rw[2 * t + 1];
    const int p0 = g_slotpos[2 * t];
    const int p1 = g_slotpos[2 * t + 1];
    const uint2* ya = (const uint2*)g_y16 + (size_t)p0 * 256;
    const uint2* yb = (const uint2*)g_y16 + (size_t)p1 * 256;
    uint2 a[4], b[4];
#pragma unroll
    for (int r = 0; r < 4; r++) { a[r] = ya[c0 + r * 64]; b[r] = yb[c0 + r * 64]; }
#pragma unroll
    for (int r = 0; r < 4; r++) {
        float2 a0 = __half22float2(*reinterpret_cast<__half2*>(&a[r].x));
        float2 a1 = __half22float2(*reinterpret_cast<__half2*>(&a[r].y));
        float2 b0 = __half22float2(*reinterpret_cast<__half2*>(&b[r].x));
        float2 b1 = __half22float2(*reinterpret_cast<__half2*>(&b[r].y));
        out[(size_t)t * 256 + c0 + r * 64] =
            make_float4(w0 * a0.x + w1 * b0.x,
                        w0 * a0.y + w1 * b0.y,
                        w0 * a1.x + w1 * b1.x,
                        w0 * a1.y + w1 * b1.y);
    }
}

// ---------------- launch ---------------------------------------------------
extern "C" void kernel_launch(void* const* d_in, const int* in_sizes, int n_in,
                              void* d_out, int out_size)
{
    const float* x   = (const float*)d_in[0];
    const float* rw  = (const float*)d_in[1];
    const void*  se  = d_in[2];
    const float* Wg  = (const float*)d_in[3];
    const float* Wu  = (const float*)d_in[4];
    const float* Wd  = (const float*)d_in[5];
    float*       out = (float*)d_out;

    const int SM1 = 3 * ST1;   // 61440
    const int SM2 = 4 * ST2;   // 81920
    cudaFuncSetAttribute(gemm1_hmma, cudaFuncAttributeMaxDynamicSharedMemorySize, SM1);
    cudaFuncSetAttribute(gemm2_hmma, cudaFuncAttributeMaxDynamicSharedMemorySize, SM2);

    cvt_route<<<2049, 256>>>((const float4*)x, (const float4*)Wg,
                             (const float4*)Wu, se);
    gemm1_hmma<<<dim3(I_DIM / 64, MAX_TILES + CONV_Y), 128, SM1>>>((const float4*)Wd);
    gemm2_hmma<<<dim3(H_DIM / 128, MAX_TILES), 256, SM2>>>();
    combine_kernel<<<T_TOK / 4, 256>>>(rw, (float4*)out);
    (void)in_sizes; (void)n_in; (void)out_size;
}